// round 1
// baseline (speedup 1.0000x reference)
#include <cuda_runtime.h>

// Problem constants
#define NBLK 128
#define NTHR 256
#define BB   128               // batch
#define TT   512               // encoder steps
#define PREDN 24
#define FF   16
#define LL   8
#define HH   1024
#define FROWS (TT + PREDN - 1) // 535 feat rows
#define KT   32                // k-tile
#define UU   8                 // hidden columns per block (128 blocks * 8 = 1024)

// Persistent device state (scratch; no allocations allowed)
__device__ float g_h0[2][BB * HH];
__device__ float g_h1[2][BB * HH];
__device__ float g_p[BB * LL];
__device__ unsigned g_count = 0;
__device__ unsigned g_gen = 0;

// ---------------- grid-wide sense-reversing barrier -------------------------
__device__ __forceinline__ void gbar() {
    __syncthreads();
    if (threadIdx.x == 0) {
        __threadfence();
        volatile unsigned* vg = &g_gen;
        unsigned g = *vg;
        if (atomicAdd(&g_count, 1u) == NBLK - 1) {
            g_count = 0;
            __threadfence();
            *vg = g + 1;
        } else {
            while (*vg == g) { /* spin on L2 */ }
        }
        __threadfence();
    }
    __syncthreads();
}

// ---------------- K=1024 GEMM slice: acc[g][i] += h[b,:] . W[g*H+u0+tu, :] ---
// Block computes C[128 b][24 gate-cols]; thread (tu,tb) owns 4 b rows x 3 gates.
// Double-buffered: global tile prefetch overlaps the smem compute.
__device__ __forceinline__ void gemm_k1024(
    const float* __restrict__ hsrc,   // [BB][HH] (read .cg - written by other blocks)
    const float* __restrict__ W,      // [3*HH][HH]
    int u0, int tu, int tb, float acc[3][4],
    float* __restrict__ sh_h,         // [KT][129]
    float* __restrict__ sh_w)         // [KT][24]
{
    const int t   = threadIdx.x;
    const int lb  = t >> 1;             // 0..127 : batch row this thread stages
    const int lk  = (t & 1) << 4;       // 0 or 16 : k sub-chunk
    const int wjl = t >> 3;             // 0..31 (24 active) : gate col to stage
    const bool wact = (wjl < 24);
    const int wk4 = (t & 7) << 2;       // k offset for weight float4
    long wbase = 0;
    if (wact) {
        int g = wjl >> 3, uu = wjl & 7;
        wbase = (long)(g * HH + u0 + uu) * HH;
    }

    float4 hv0, hv1, hv2, hv3, wv;
    {   // prefetch tile 0
        const float4* hp = reinterpret_cast<const float4*>(hsrc + (long)lb * HH + lk);
        hv0 = __ldcg(hp); hv1 = __ldcg(hp + 1); hv2 = __ldcg(hp + 2); hv3 = __ldcg(hp + 3);
        if (wact) wv = *reinterpret_cast<const float4*>(W + wbase + wk4);
    }

    for (int k0 = 0; k0 < HH; k0 += KT) {
        __syncthreads();   // previous tile's compute done
        // stage h tile (transposed: sh_h[k][b])
        sh_h[(lk + 0) * 129 + lb] = hv0.x; sh_h[(lk + 1) * 129 + lb] = hv0.y;
        sh_h[(lk + 2) * 129 + lb] = hv0.z; sh_h[(lk + 3) * 129 + lb] = hv0.w;
        sh_h[(lk + 4) * 129 + lb] = hv1.x; sh_h[(lk + 5) * 129 + lb] = hv1.y;
        sh_h[(lk + 6) * 129 + lb] = hv1.z; sh_h[(lk + 7) * 129 + lb] = hv1.w;
        sh_h[(lk + 8) * 129 + lb] = hv2.x; sh_h[(lk + 9) * 129 + lb] = hv2.y;
        sh_h[(lk + 10) * 129 + lb] = hv2.z; sh_h[(lk + 11) * 129 + lb] = hv2.w;
        sh_h[(lk + 12) * 129 + lb] = hv3.x; sh_h[(lk + 13) * 129 + lb] = hv3.y;
        sh_h[(lk + 14) * 129 + lb] = hv3.z; sh_h[(lk + 15) * 129 + lb] = hv3.w;
        if (wact) {
            sh_w[(wk4 + 0) * 24 + wjl] = wv.x; sh_w[(wk4 + 1) * 24 + wjl] = wv.y;
            sh_w[(wk4 + 2) * 24 + wjl] = wv.z; sh_w[(wk4 + 3) * 24 + wjl] = wv.w;
        }
        __syncthreads();

        int kn = k0 + KT;
        if (kn < HH) {      // prefetch next tile while computing this one
            const float4* hp = reinterpret_cast<const float4*>(hsrc + (long)lb * HH + kn + lk);
            hv0 = __ldcg(hp); hv1 = __ldcg(hp + 1); hv2 = __ldcg(hp + 2); hv3 = __ldcg(hp + 3);
            if (wact) wv = *reinterpret_cast<const float4*>(W + wbase + kn + wk4);
        }

        #pragma unroll
        for (int kk = 0; kk < KT; kk++) {
            float w0 = sh_w[kk * 24 + tu];
            float w1 = sh_w[kk * 24 + 8 + tu];
            float w2 = sh_w[kk * 24 + 16 + tu];
            float h0 = sh_h[kk * 129 + tb];
            float h1 = sh_h[kk * 129 + 32 + tb];
            float h2 = sh_h[kk * 129 + 64 + tb];
            float h3 = sh_h[kk * 129 + 96 + tb];
            acc[0][0] += h0 * w0; acc[0][1] += h1 * w0; acc[0][2] += h2 * w0; acc[0][3] += h3 * w0;
            acc[1][0] += h0 * w1; acc[1][1] += h1 * w1; acc[1][2] += h2 * w1; acc[1][3] += h3 * w1;
            acc[2][0] += h0 * w2; acc[2][1] += h1 * w2; acc[2][2] += h2 * w2; acc[2][3] += h3 * w2;
        }
    }
}

// ---------------- small input projection (K = 24) ---------------------------
__device__ __forceinline__ void load_wi_slice(const float* __restrict__ Wih, int u0,
                                              float* __restrict__ sh_wi) {
    for (int idx = threadIdx.x; idx < 24 * 24; idx += NTHR) {
        int jl = idx / 24, k = idx % 24;
        int g = jl >> 3, uu = jl & 7;
        sh_wi[k * 24 + jl] = Wih[(long)(g * HH + u0 + uu) * 24 + k];
    }
}

__device__ __forceinline__ void input_acc24(const float* __restrict__ sh_x,
                                            const float* __restrict__ sh_wi,
                                            int tu, int tb, float acc[3][4]) {
    #pragma unroll
    for (int k = 0; k < 24; k++) {
        float w0 = sh_wi[k * 24 + tu];
        float w1 = sh_wi[k * 24 + 8 + tu];
        float w2 = sh_wi[k * 24 + 16 + tu];
        #pragma unroll
        for (int i = 0; i < 4; i++) {
            float xv = sh_x[(tb + 32 * i) * 25 + k];
            acc[0][i] += xv * w0; acc[1][i] += xv * w1; acc[2][i] += xv * w2;
        }
    }
}

// ---------------- GRU pointwise update --------------------------------------
__device__ __forceinline__ void gru_update(const float ai[3][4], const float ah[3][4],
                                           const float* __restrict__ bih,
                                           const float* __restrict__ bhh,
                                           int jcol, int tb,
                                           const float* __restrict__ hcur,
                                           float* __restrict__ hnxt) {
    float bir = bih[jcol], biz = bih[HH + jcol], bin = bih[2 * HH + jcol];
    float bhr = bhh[jcol], bhz = bhh[HH + jcol], bhn = bhh[2 * HH + jcol];
    #pragma unroll
    for (int i = 0; i < 4; i++) {
        int b = tb + 32 * i;
        float r = 1.f / (1.f + __expf(-(ai[0][i] + bir + ah[0][i] + bhr)));
        float z = 1.f / (1.f + __expf(-(ai[1][i] + biz + ah[1][i] + bhz)));
        float n = tanhf(ai[2][i] + bin + r * (ah[2][i] + bhn));
        float ho = __ldcg(hcur + (long)b * HH + jcol);
        __stcg(hnxt + (long)b * HH + jcol, (1.f - z) * n + z * ho);
    }
}

// ---------------- FC head: out[b,l] = h[b,:].fc_W[l,:] + fc_b[l] ------------
// block b handles batch row b; warp w handles output l = w.
__device__ __forceinline__ void fc_phase(const float* __restrict__ h,
                                         const float* __restrict__ fcW,
                                         const float* __restrict__ fcb,
                                         float* __restrict__ outp) {
    int b = blockIdx.x;
    int w = threadIdx.x >> 5;
    int lane = threadIdx.x & 31;
    float s = 0.f;
    #pragma unroll
    for (int c = 0; c < 32; c++)
        s += __ldcg(h + (long)b * HH + 32 * c + lane) * fcW[(long)w * HH + 32 * c + lane];
    #pragma unroll
    for (int o = 16; o; o >>= 1) s += __shfl_down_sync(0xffffffffu, s, o);
    if (lane == 0) {
        float v = s + fcb[w];
        outp[b * LL + w] = v;
        __stcg(g_p + b * LL + w, v);
    }
}

// ---------------- persistent kernel -----------------------------------------
__global__ void __launch_bounds__(NTHR, 1) gru_persistent(
    const float* __restrict__ feats, const float* __restrict__ labels,
    const float* __restrict__ y, const int* __restrict__ teacher,
    const float* __restrict__ eWih0, const float* __restrict__ eWhh0,
    const float* __restrict__ ebih0, const float* __restrict__ ebhh0,
    const float* __restrict__ eWih1, const float* __restrict__ eWhh1,
    const float* __restrict__ ebih1, const float* __restrict__ ebhh1,
    const float* __restrict__ dWih, const float* __restrict__ dWhh,
    const float* __restrict__ dbih, const float* __restrict__ dbhh,
    const float* __restrict__ fcW, const float* __restrict__ fcb,
    float* __restrict__ out)
{
    __shared__ float sh_h[KT * 129];
    __shared__ float sh_w[KT * 24];
    __shared__ float sh_x[BB * 25];
    __shared__ float sh_wi[24 * 24];

    const int t = threadIdx.x;
    const int tu = t & 7;
    const int tb = t >> 3;
    const int u0 = blockIdx.x * UU;
    const int jcol = u0 + tu;
    const int teach = teacher[0];

    // zero-init hidden state ping buffers (cur = 0)
    for (int i = blockIdx.x * NTHR + t; i < BB * HH; i += NBLK * NTHR) {
        g_h0[0][i] = 0.f;
        g_h1[0][i] = 0.f;
    }
    load_wi_slice(eWih0, u0, sh_wi);
    gbar();

    int cur = 0;
    // ================= encoder: fused 2-layer scan ==========================
    for (int step = 0; step < TT; step++) {
        // stage x_t = concat(feats[:,step,:16], labels[:,step,:8])
        for (int idx = t; idx < BB * 24; idx += NTHR) {
            int b = idx / 24, k = idx % 24;
            float v = (k < FF) ? feats[((long)b * FROWS + step) * FF + k]
                               : labels[((long)b * TT + step) * LL + (k - FF)];
            sh_x[b * 25 + k] = v;
        }
        __syncthreads();

        // layer 0
        {
            float ai[3][4] = {}; float ah[3][4] = {};
            input_acc24(sh_x, sh_wi, tu, tb, ai);
            gemm_k1024(g_h0[cur], eWhh0, u0, tu, tb, ah, sh_h, sh_w);
            gru_update(ai, ah, ebih0, ebhh0, jcol, tb, g_h0[cur], g_h0[cur ^ 1]);
        }
        gbar();

        // layer 1 (input = fresh h0)
        {
            float bi[3][4] = {}; float bh[3][4] = {};
            gemm_k1024(g_h0[cur ^ 1], eWih1, u0, tu, tb, bi, sh_h, sh_w);
            gemm_k1024(g_h1[cur],     eWhh1, u0, tu, tb, bh, sh_h, sh_w);
            gru_update(bi, bh, ebih1, ebhh1, jcol, tb, g_h1[cur], g_h1[cur ^ 1]);
        }
        gbar();
        cur ^= 1;
    }

    // ps = h_final @ fcW^T + fcb  -> out step 0, and seed g_p
    fc_phase(g_h1[cur], fcW, fcb, out);
    load_wi_slice(dWih, u0, sh_wi);
    gbar();

    // ================= decoder: 23 autoregressive steps =====================
    for (int s = 0; s < PREDN - 1; s++) {
        for (int idx = t; idx < BB * 24; idx += NTHR) {
            int b = idx / 24, k = idx % 24;
            float v;
            if (k < FF)      v = feats[((long)b * FROWS + TT + s) * FF + k];
            else if (teach)  v = y[((long)b * (PREDN - 1) + s) * LL + (k - FF)];
            else             v = __ldcg(g_p + b * LL + (k - FF));
            sh_x[b * 25 + k] = v;
        }
        __syncthreads();

        float ai[3][4] = {}; float ah[3][4] = {};
        input_acc24(sh_x, sh_wi, tu, tb, ai);
        gemm_k1024(g_h1[cur], dWhh, u0, tu, tb, ah, sh_h, sh_w);
        gru_update(ai, ah, dbih, dbhh, jcol, tb, g_h1[cur], g_h1[cur ^ 1]);
        gbar();

        fc_phase(g_h1[cur ^ 1], fcW, fcb, out + (long)(s + 1) * BB * LL);
        gbar();
        cur ^= 1;
    }
}

extern "C" void kernel_launch(void* const* d_in, const int* in_sizes, int n_in,
                              void* d_out, int out_size) {
    const float* feats  = (const float*)d_in[0];
    const float* labels = (const float*)d_in[1];
    const float* y      = (const float*)d_in[2];
    const int*   teach  = (const int*)d_in[3];
    const float* eWih0  = (const float*)d_in[4];
    const float* eWhh0  = (const float*)d_in[5];
    const float* ebih0  = (const float*)d_in[6];
    const float* ebhh0  = (const float*)d_in[7];
    const float* eWih1  = (const float*)d_in[8];
    const float* eWhh1  = (const float*)d_in[9];
    const float* ebih1  = (const float*)d_in[10];
    const float* ebhh1  = (const float*)d_in[11];
    const float* dWih   = (const float*)d_in[12];
    const float* dWhh   = (const float*)d_in[13];
    const float* dbih   = (const float*)d_in[14];
    const float* dbhh   = (const float*)d_in[15];
    const float* fcW    = (const float*)d_in[16];
    const float* fcb    = (const float*)d_in[17];
    float* out = (float*)d_out;

    gru_persistent<<<NBLK, NTHR>>>(feats, labels, y, teach,
                                   eWih0, eWhh0, ebih0, ebhh0,
                                   eWih1, eWhh1, ebih1, ebhh1,
                                   dWih, dWhh, dbih, dbhh,
                                   fcW, fcb, out);
}